// round 15
// baseline (speedup 1.0000x reference)
#include <cuda_runtime.h>
#include <math.h>

// ---------------------------------------------------------------------------
// StackTransformerSquash: B=8, T=2048, F=128, LATENT_FRAME=4 -> Tl=512,
// D=1024, H=8, Dh=128, 6 post-norm encoder layers with non-causal ALiBi,
// exact GELU, D_FF=1024, then post projection.
//
// All GEMMs are fp32 FFMA tiled SGEMM (128x128x16 tiles, 8x8/thread,
// double-buffered smem with register prefetch). Two variants:
//   gemm_tn : C = A(MxK) * B(NxK)^T  (+bias, +optional exact GELU), batched
//   gemm_nn : C = A(MxK) * B(KxN)                                , batched
// Batch (z) offsets are expressed as (b, h) strides with z = b*8 + h so the
// same kernels serve plain GEMMs (gridDim.z == 1) and per-(batch,head)
// attention GEMMs (gridDim.z == 64).
// ---------------------------------------------------------------------------

#define BM 128
#define BN 128
#define BK 16

// Scratch buffers (allocation-free rule: __device__ globals).
__device__ float g_X  [8 * 512 * 1024];   // residual stream          16 MB
__device__ float g_QKV[8 * 512 * 3072];   // fused qkv                48 MB
__device__ float g_S  [8 * 8 * 512 * 512];// attention scores/probs   64 MB
__device__ float g_O  [8 * 512 * 1024];   // attention output         16 MB
__device__ float g_T1 [8 * 512 * 1024];   // temp                     16 MB
__device__ float g_T2 [8 * 512 * 1024];   // temp                     16 MB

__device__ __forceinline__ float gelu_exact(float x) {
    return 0.5f * x * (1.0f + erff(x * 0.70710678118654752f));
}

// ---------------------------------------------------------------------------
// TN GEMM: C[m][n] = sum_k A[m][k] * B[n][k]  (+ bias[n], + gelu)
// EPI: 0 = none, 1 = bias, 2 = bias + exact gelu
// ---------------------------------------------------------------------------
template <int EPI>
__global__ void __launch_bounds__(256, 2)
gemm_tn(const float* __restrict__ A, int lda, long sAb, long sAh,
        const float* __restrict__ B, int ldb, long sBb, long sBh,
        const float* __restrict__ bias,
        float* __restrict__ C, int ldc, long sCb, long sCh,
        int K)
{
    const int tid = threadIdx.x;
    const int z   = blockIdx.z;
    const int zb  = z >> 3;
    const int zh  = z & 7;
    A += (long)zb * sAb + (long)zh * sAh;
    B += (long)zb * sBb + (long)zh * sBh;
    C += (long)zb * sCb + (long)zh * sCh;

    const int m0 = blockIdx.y * BM;
    const int n0 = blockIdx.x * BN;

    __shared__ float As[2][BK][BM];
    __shared__ float Bs[2][BK][BN];

    // Global loaders: 128 rows x 16 k per operand. Each thread: 2x float4.
    const int lrow = tid >> 2;          // 0..63
    const int lcol = (tid & 3) << 2;    // 0,4,8,12

    const float* pA = A + (long)(m0 + lrow) * lda + lcol;
    const float* pB = B + (long)(n0 + lrow) * ldb + lcol;

    // Compute mapping: warp = 4x8 lanes; 8 warps tiled 4x2.
    const int w    = tid >> 5;
    const int lane = tid & 31;
    const int ty   = ((w >> 1) << 2) + (lane >> 3);  // 0..15 (M groups of 8)
    const int tx   = ((w & 1) << 3) + (lane & 7);    // 0..15 (N groups of 8)

    float acc[8][8];
#pragma unroll
    for (int i = 0; i < 8; i++)
#pragma unroll
        for (int j = 0; j < 8; j++) acc[i][j] = 0.0f;

    float4 ra0 = *(const float4*)pA;
    float4 ra1 = *(const float4*)(pA + 64L * lda);
    float4 rb0 = *(const float4*)pB;
    float4 rb1 = *(const float4*)(pB + 64L * ldb);

    As[0][lcol + 0][lrow]      = ra0.x;
    As[0][lcol + 1][lrow]      = ra0.y;
    As[0][lcol + 2][lrow]      = ra0.z;
    As[0][lcol + 3][lrow]      = ra0.w;
    As[0][lcol + 0][lrow + 64] = ra1.x;
    As[0][lcol + 1][lrow + 64] = ra1.y;
    As[0][lcol + 2][lrow + 64] = ra1.z;
    As[0][lcol + 3][lrow + 64] = ra1.w;
    Bs[0][lcol + 0][lrow]      = rb0.x;
    Bs[0][lcol + 1][lrow]      = rb0.y;
    Bs[0][lcol + 2][lrow]      = rb0.z;
    Bs[0][lcol + 3][lrow]      = rb0.w;
    Bs[0][lcol + 0][lrow + 64] = rb1.x;
    Bs[0][lcol + 1][lrow + 64] = rb1.y;
    Bs[0][lcol + 2][lrow + 64] = rb1.z;
    Bs[0][lcol + 3][lrow + 64] = rb1.w;
    __syncthreads();

    int st = 0;
    const int KT = K >> 4;
    for (int kt = 0; kt < KT; kt++) {
        if (kt + 1 < KT) {
            const float* qA = pA + (kt + 1) * BK;
            const float* qB = pB + (kt + 1) * BK;
            ra0 = *(const float4*)qA;
            ra1 = *(const float4*)(qA + 64L * lda);
            rb0 = *(const float4*)qB;
            rb1 = *(const float4*)(qB + 64L * ldb);
        }
#pragma unroll
        for (int k = 0; k < BK; k++) {
            float a[8], b[8];
            *(float4*)(a)     = *(const float4*)&As[st][k][ty * 8];
            *(float4*)(a + 4) = *(const float4*)&As[st][k][ty * 8 + 4];
            *(float4*)(b)     = *(const float4*)&Bs[st][k][tx * 8];
            *(float4*)(b + 4) = *(const float4*)&Bs[st][k][tx * 8 + 4];
#pragma unroll
            for (int i = 0; i < 8; i++)
#pragma unroll
                for (int j = 0; j < 8; j++) acc[i][j] += a[i] * b[j];
        }
        if (kt + 1 < KT) {
            st ^= 1;
            As[st][lcol + 0][lrow]      = ra0.x;
            As[st][lcol + 1][lrow]      = ra0.y;
            As[st][lcol + 2][lrow]      = ra0.z;
            As[st][lcol + 3][lrow]      = ra0.w;
            As[st][lcol + 0][lrow + 64] = ra1.x;
            As[st][lcol + 1][lrow + 64] = ra1.y;
            As[st][lcol + 2][lrow + 64] = ra1.z;
            As[st][lcol + 3][lrow + 64] = ra1.w;
            Bs[st][lcol + 0][lrow]      = rb0.x;
            Bs[st][lcol + 1][lrow]      = rb0.y;
            Bs[st][lcol + 2][lrow]      = rb0.z;
            Bs[st][lcol + 3][lrow]      = rb0.w;
            Bs[st][lcol + 0][lrow + 64] = rb1.x;
            Bs[st][lcol + 1][lrow + 64] = rb1.y;
            Bs[st][lcol + 2][lrow + 64] = rb1.z;
            Bs[st][lcol + 3][lrow + 64] = rb1.w;
            __syncthreads();
        }
    }

    const int crow = m0 + ty * 8;
    const int ccol = n0 + tx * 8;
    float bv[8];
    if (EPI >= 1) {
#pragma unroll
        for (int j = 0; j < 8; j++) bv[j] = bias[ccol + j];
    }
#pragma unroll
    for (int i = 0; i < 8; i++) {
        float o[8];
#pragma unroll
        for (int j = 0; j < 8; j++) {
            float v = acc[i][j];
            if (EPI >= 1) v += bv[j];
            if (EPI == 2) v = gelu_exact(v);
            o[j] = v;
        }
        *(float4*)&C[(long)(crow + i) * ldc + ccol]     = *(float4*)o;
        *(float4*)&C[(long)(crow + i) * ldc + ccol + 4] = *(float4*)(o + 4);
    }
}

// ---------------------------------------------------------------------------
// NN GEMM: C[m][n] = sum_k A[m][k] * B[k][n]   (no bias; used for P @ V)
// ---------------------------------------------------------------------------
__global__ void __launch_bounds__(256, 2)
gemm_nn(const float* __restrict__ A, int lda, long sAb, long sAh,
        const float* __restrict__ B, int ldb, long sBb, long sBh,
        float* __restrict__ C, int ldc, long sCb, long sCh,
        int K)
{
    const int tid = threadIdx.x;
    const int z   = blockIdx.z;
    const int zb  = z >> 3;
    const int zh  = z & 7;
    A += (long)zb * sAb + (long)zh * sAh;
    B += (long)zb * sBb + (long)zh * sBh;
    C += (long)zb * sCb + (long)zh * sCh;

    const int m0 = blockIdx.y * BM;
    const int n0 = blockIdx.x * BN;

    __shared__ float As[2][BK][BM];
    __shared__ float Bs[2][BK][BN];

    const int lrow = tid >> 2;           // A loader: 0..63
    const int lcol = (tid & 3) << 2;
    const float* pA = A + (long)(m0 + lrow) * lda + lcol;

    const int bkrow = tid >> 4;          // B loader: k-row 0..15
    const int bncol = (tid & 15) << 3;   // n col 0..120 (2 float4)
    const float* pB = B + (long)bkrow * ldb + n0 + bncol;

    const int w    = tid >> 5;
    const int lane = tid & 31;
    const int ty   = ((w >> 1) << 2) + (lane >> 3);
    const int tx   = ((w & 1) << 3) + (lane & 7);

    float acc[8][8];
#pragma unroll
    for (int i = 0; i < 8; i++)
#pragma unroll
        for (int j = 0; j < 8; j++) acc[i][j] = 0.0f;

    float4 ra0 = *(const float4*)pA;
    float4 ra1 = *(const float4*)(pA + 64L * lda);
    float4 rb0 = *(const float4*)pB;
    float4 rb1 = *(const float4*)(pB + 4);

    As[0][lcol + 0][lrow]      = ra0.x;
    As[0][lcol + 1][lrow]      = ra0.y;
    As[0][lcol + 2][lrow]      = ra0.z;
    As[0][lcol + 3][lrow]      = ra0.w;
    As[0][lcol + 0][lrow + 64] = ra1.x;
    As[0][lcol + 1][lrow + 64] = ra1.y;
    As[0][lcol + 2][lrow + 64] = ra1.z;
    As[0][lcol + 3][lrow + 64] = ra1.w;
    *(float4*)&Bs[0][bkrow][bncol]     = rb0;
    *(float4*)&Bs[0][bkrow][bncol + 4] = rb1;
    __syncthreads();

    int st = 0;
    const int KT = K >> 4;
    for (int kt = 0; kt < KT; kt++) {
        if (kt + 1 < KT) {
            const float* qA = pA + (kt + 1) * BK;
            const float* qB = pB + (long)(kt + 1) * BK * ldb;
            ra0 = *(const float4*)qA;
            ra1 = *(const float4*)(qA + 64L * lda);
            rb0 = *(const float4*)qB;
            rb1 = *(const float4*)(qB + 4);
        }
#pragma unroll
        for (int k = 0; k < BK; k++) {
            float a[8], b[8];
            *(float4*)(a)     = *(const float4*)&As[st][k][ty * 8];
            *(float4*)(a + 4) = *(const float4*)&As[st][k][ty * 8 + 4];
            *(float4*)(b)     = *(const float4*)&Bs[st][k][tx * 8];
            *(float4*)(b + 4) = *(const float4*)&Bs[st][k][tx * 8 + 4];
#pragma unroll
            for (int i = 0; i < 8; i++)
#pragma unroll
                for (int j = 0; j < 8; j++) acc[i][j] += a[i] * b[j];
        }
        if (kt + 1 < KT) {
            st ^= 1;
            As[st][lcol + 0][lrow]      = ra0.x;
            As[st][lcol + 1][lrow]      = ra0.y;
            As[st][lcol + 2][lrow]      = ra0.z;
            As[st][lcol + 3][lrow]      = ra0.w;
            As[st][lcol + 0][lrow + 64] = ra1.x;
            As[st][lcol + 1][lrow + 64] = ra1.y;
            As[st][lcol + 2][lrow + 64] = ra1.z;
            As[st][lcol + 3][lrow + 64] = ra1.w;
            *(float4*)&Bs[st][bkrow][bncol]     = rb0;
            *(float4*)&Bs[st][bkrow][bncol + 4] = rb1;
            __syncthreads();
        }
    }

    const int crow = m0 + ty * 8;
    const int ccol = n0 + tx * 8;
#pragma unroll
    for (int i = 0; i < 8; i++) {
        *(float4*)&C[(long)(crow + i) * ldc + ccol]     = *(float4*)&acc[i][0];
        *(float4*)&C[(long)(crow + i) * ldc + ccol + 4] = *(float4*)&acc[i][4];
    }
}

// ---------------------------------------------------------------------------
// Fused ALiBi + softmax over rows of S (row = ((b*8+h)*512 + i), width 512).
// val = S * (1/sqrt(128)) - slope_h * |i - j| ; in-place softmax.
// ---------------------------------------------------------------------------
__global__ void __launch_bounds__(256)
softmax_alibi(float* __restrict__ S)
{
    const int r = blockIdx.x;
    const int i = r & 511;
    const int h = (r >> 9) & 7;
    const float slope = exp2f(-(float)(h + 1));
    float* row = S + (long)r * 512;

    const int t = threadIdx.x;
    const float sc = 0.08838834764831845f;   // 1/sqrt(128)

    float2 v = *(float2*)(row + 2 * t);
    const float fi = (float)i;
    const float j0 = (float)(2 * t);
    float v0 = v.x * sc - slope * fabsf(fi - j0);
    float v1 = v.y * sc - slope * fabsf(fi - (j0 + 1.0f));

    __shared__ float sh[8];
    __shared__ float bc;

    // max reduce
    float m = fmaxf(v0, v1);
#pragma unroll
    for (int o = 16; o; o >>= 1) m = fmaxf(m, __shfl_xor_sync(0xffffffffu, m, o));
    if ((t & 31) == 0) sh[t >> 5] = m;
    __syncthreads();
    if (t == 0) {
        float mm = sh[0];
#pragma unroll
        for (int q = 1; q < 8; q++) mm = fmaxf(mm, sh[q]);
        bc = mm;
    }
    __syncthreads();
    m = bc;

    float e0 = expf(v0 - m);
    float e1 = expf(v1 - m);
    float s = e0 + e1;
#pragma unroll
    for (int o = 16; o; o >>= 1) s += __shfl_xor_sync(0xffffffffu, s, o);
    __syncthreads();               // protect sh[] reuse
    if ((t & 31) == 0) sh[t >> 5] = s;
    __syncthreads();
    if (t == 0) {
        float ss = sh[0];
#pragma unroll
        for (int q = 1; q < 8; q++) ss += sh[q];
        bc = 1.0f / ss;
    }
    __syncthreads();
    const float inv = bc;

    float2 o;
    o.x = e0 * inv;
    o.y = e1 * inv;
    *(float2*)(row + 2 * t) = o;
}

// ---------------------------------------------------------------------------
// out = LayerNorm(x + y) * g + b, row width 1024, one block per row.
// ---------------------------------------------------------------------------
__global__ void __launch_bounds__(256)
add_ln(const float* __restrict__ X, const float* __restrict__ Y,
       const float* __restrict__ G, const float* __restrict__ Bt,
       float* __restrict__ O)
{
    const int row = blockIdx.x;
    const long base = (long)row * 1024;
    const int t = threadIdx.x;

    float4 vx = *(const float4*)(X + base + 4 * t);
    float4 vy = *(const float4*)(Y + base + 4 * t);
    float a0 = vx.x + vy.x;
    float a1 = vx.y + vy.y;
    float a2 = vx.z + vy.z;
    float a3 = vx.w + vy.w;

    float s = a0 + a1 + a2 + a3;
    float q = a0 * a0 + a1 * a1 + a2 * a2 + a3 * a3;

    __shared__ float2 sh[8];
    __shared__ float2 res;
#pragma unroll
    for (int o = 16; o; o >>= 1) {
        s += __shfl_xor_sync(0xffffffffu, s, o);
        q += __shfl_xor_sync(0xffffffffu, q, o);
    }
    if ((t & 31) == 0) sh[t >> 5] = make_float2(s, q);
    __syncthreads();
    if (t == 0) {
        float ss = 0.0f, qq = 0.0f;
#pragma unroll
        for (int k = 0; k < 8; k++) { ss += sh[k].x; qq += sh[k].y; }
        res = make_float2(ss, qq);
    }
    __syncthreads();

    const float mean = res.x * (1.0f / 1024.0f);
    const float var  = res.y * (1.0f / 1024.0f) - mean * mean;
    const float inv  = rsqrtf(var + 1e-5f);

    float4 g4 = *(const float4*)(G + 4 * t);
    float4 b4 = *(const float4*)(Bt + 4 * t);
    float4 o;
    o.x = (a0 - mean) * inv * g4.x + b4.x;
    o.y = (a1 - mean) * inv * g4.y + b4.y;
    o.z = (a2 - mean) * inv * g4.z + b4.z;
    o.w = (a3 - mean) * inv * g4.w + b4.w;
    *(float4*)(O + base + 4 * t) = o;
}

// ---------------------------------------------------------------------------
// Host orchestration
// ---------------------------------------------------------------------------
extern "C" void kernel_launch(void* const* d_in, const int* in_sizes, int n_in,
                              void* d_out, int out_size)
{
    (void)in_sizes; (void)n_in; (void)out_size;

    const float* x      = (const float*)d_in[0];   // (8,2048,128) == (4096,512)
    const float* pre_w  = (const float*)d_in[1];   // (1024,512)
    const float* pre_b  = (const float*)d_in[2];   // (1024)
    const float* in_w   = (const float*)d_in[3];   // (6,3072,1024)
    const float* in_b   = (const float*)d_in[4];   // (6,3072)
    const float* out_w  = (const float*)d_in[5];   // (6,1024,1024)
    const float* out_b  = (const float*)d_in[6];   // (6,1024)
    const float* ln1_g  = (const float*)d_in[7];
    const float* ln1_b  = (const float*)d_in[8];
    const float* ff1_w  = (const float*)d_in[9];   // (6,1024,1024)
    const float* ff1_b  = (const float*)d_in[10];
    const float* ff2_w  = (const float*)d_in[11];  // (6,1024,1024)
    const float* ff2_b  = (const float*)d_in[12];
    const float* ln2_g  = (const float*)d_in[13];
    const float* ln2_b  = (const float*)d_in[14];
    const float* post_w = (const float*)d_in[15];  // (1024,1024)
    const float* post_b = (const float*)d_in[16];

    float *X, *QKV, *S, *O, *T1, *T2;
    cudaGetSymbolAddress((void**)&X,   g_X);
    cudaGetSymbolAddress((void**)&QKV, g_QKV);
    cudaGetSymbolAddress((void**)&S,   g_S);
    cudaGetSymbolAddress((void**)&O,   g_O);
    cudaGetSymbolAddress((void**)&T1,  g_T1);
    cudaGetSymbolAddress((void**)&T2,  g_T2);

    const dim3 blk(256);

    // pre-projection: (4096,512) @ (1024,512)^T -> X (4096,1024)
    gemm_tn<1><<<dim3(8, 32, 1), blk>>>(
        x, 512, 0, 0,  pre_w, 512, 0, 0,  pre_b,
        X, 1024, 0, 0,  512);

    const long sQKVb = 512L * 3072;     // per-batch stride inside QKV
    const long sSb   = 8L * 512 * 512;  // per-batch stride inside S
    const long sSh   = 512L * 512;      // per-head stride inside S
    const long sXb   = 512L * 1024;     // per-batch stride inside X/O

    for (int l = 0; l < 6; l++) {
        const float* iw  = in_w  + (long)l * 3072 * 1024;
        const float* ib  = in_b  + (long)l * 3072;
        const float* ow  = out_w + (long)l * 1024 * 1024;
        const float* ob  = out_b + (long)l * 1024;
        const float* f1w = ff1_w + (long)l * 1024 * 1024;
        const float* f1b = ff1_b + (long)l * 1024;
        const float* f2w = ff2_w + (long)l * 1024 * 1024;
        const float* f2b = ff2_b + (long)l * 1024;
        const float* g1  = ln1_g + (long)l * 1024;
        const float* b1  = ln1_b + (long)l * 1024;
        const float* g2  = ln2_g + (long)l * 1024;
        const float* b2  = ln2_b + (long)l * 1024;

        // QKV = X @ in_w^T + in_b : (4096,1024) x (3072,1024)^T
        gemm_tn<1><<<dim3(24, 32, 1), blk>>>(
            X, 1024, 0, 0,  iw, 1024, 0, 0,  ib,
            QKV, 3072, 0, 0,  1024);

        // scores S[b,h] = Q[b,h] @ K[b,h]^T  (512x512, K=128), z = b*8+h
        gemm_tn<0><<<dim3(4, 4, 64), blk>>>(
            QKV,        3072, sQKVb, 128,
            QKV + 1024, 3072, sQKVb, 128,
            nullptr,
            S, 512, sSb, sSh,  128);

        // softmax with ALiBi + 1/sqrt(Dh) scale (in place)
        softmax_alibi<<<32768, blk>>>(S);

        // O[b,h] = P[b,h] @ V[b,h]  (512x128, K=512)
        gemm_nn<<<dim3(1, 4, 64), blk>>>(
            S,          512,  sSb,   sSh,
            QKV + 2048, 3072, sQKVb, 128,
            O, 1024, sXb, 128,  512);

        // attention output projection
        gemm_tn<1><<<dim3(8, 32, 1), blk>>>(
            O, 1024, 0, 0,  ow, 1024, 0, 0,  ob,
            T1, 1024, 0, 0,  1024);

        // X = LN(X + T1)
        add_ln<<<4096, blk>>>(X, T1, g1, b1, X);

        // FF1 (+ exact GELU)
        gemm_tn<2><<<dim3(8, 32, 1), blk>>>(
            X, 1024, 0, 0,  f1w, 1024, 0, 0,  f1b,
            T1, 1024, 0, 0,  1024);

        // FF2
        gemm_tn<1><<<dim3(8, 32, 1), blk>>>(
            T1, 1024, 0, 0,  f2w, 1024, 0, 0,  f2b,
            T2, 1024, 0, 0,  1024);

        // X = LN(X + T2)
        add_ln<<<4096, blk>>>(X, T2, g2, b2, X);
    }

    // post projection -> d_out (4096,1024)
    gemm_tn<1><<<dim3(8, 32, 1), blk>>>(
        X, 1024, 0, 0,  post_w, 1024, 0, 0,  post_b,
        (float*)d_out, 1024, 0, 0,  1024);
}

// round 16
// speedup vs baseline: 1.0554x; 1.0554x over previous
#include <cuda_runtime.h>
#include <math.h>

// ---------------------------------------------------------------------------
// StackTransformerSquash: B=8, T=2048, F=128, LATENT_FRAME=4 -> Tl=512,
// D=1024, H=8, Dh=128, 6 post-norm encoder layers with non-causal ALiBi,
// exact GELU, D_FF=1024, then post projection.
//
// All GEMMs are fp32 FFMA tiled SGEMM (128x128x16 tiles, 8x8/thread,
// double-buffered smem with register prefetch). Two variants:
//   gemm_tn : C = A(MxK) * B(NxK)^T  (+bias, +optional exact GELU), batched
//   gemm_nn : C = A(MxK) * B(KxN)                                , batched
// Batch (z) offsets are expressed as (b, h) strides with z = b*8 + h so the
// same kernels serve plain GEMMs (gridDim.z == 1) and per-(batch,head)
// attention GEMMs (gridDim.z == 64).
// ---------------------------------------------------------------------------

#define BM 128
#define BN 128
#define BK 16

// Scratch buffers (allocation-free rule: __device__ globals).
__device__ float g_X  [8 * 512 * 1024];   // residual stream          16 MB
__device__ float g_QKV[8 * 512 * 3072];   // fused qkv                48 MB
__device__ float g_S  [8 * 8 * 512 * 512];// attention scores/probs   64 MB
__device__ float g_O  [8 * 512 * 1024];   // attention output         16 MB
__device__ float g_T1 [8 * 512 * 1024];   // temp                     16 MB
__device__ float g_T2 [8 * 512 * 1024];   // temp                     16 MB

__device__ __forceinline__ float gelu_exact(float x) {
    return 0.5f * x * (1.0f + erff(x * 0.70710678118654752f));
}

// ---------------------------------------------------------------------------
// TN GEMM: C[m][n] = sum_k A[m][k] * B[n][k]  (+ bias[n], + gelu)
// EPI: 0 = none, 1 = bias, 2 = bias + exact gelu
// ---------------------------------------------------------------------------
template <int EPI>
__global__ void __launch_bounds__(256, 2)
gemm_tn(const float* __restrict__ A, int lda, long sAb, long sAh,
        const float* __restrict__ B, int ldb, long sBb, long sBh,
        const float* __restrict__ bias,
        float* __restrict__ C, int ldc, long sCb, long sCh,
        int K)
{
    const int tid = threadIdx.x;
    const int z   = blockIdx.z;
    const int zb  = z >> 3;
    const int zh  = z & 7;
    A += (long)zb * sAb + (long)zh * sAh;
    B += (long)zb * sBb + (long)zh * sBh;
    C += (long)zb * sCb + (long)zh * sCh;

    const int m0 = blockIdx.y * BM;
    const int n0 = blockIdx.x * BN;

    __shared__ float As[2][BK][BM];
    __shared__ float Bs[2][BK][BN];

    // Global loaders: 128 rows x 16 k per operand. Each thread: 2x float4.
    const int lrow = tid >> 2;          // 0..63
    const int lcol = (tid & 3) << 2;    // 0,4,8,12

    const float* pA = A + (long)(m0 + lrow) * lda + lcol;
    const float* pB = B + (long)(n0 + lrow) * ldb + lcol;

    // Compute mapping: warp = 4x8 lanes; 8 warps tiled 4x2.
    const int w    = tid >> 5;
    const int lane = tid & 31;
    const int ty   = ((w >> 1) << 2) + (lane >> 3);  // 0..15 (M groups of 8)
    const int tx   = ((w & 1) << 3) + (lane & 7);    // 0..15 (N groups of 8)

    float acc[8][8];
#pragma unroll
    for (int i = 0; i < 8; i++)
#pragma unroll
        for (int j = 0; j < 8; j++) acc[i][j] = 0.0f;

    float4 ra0 = *(const float4*)pA;
    float4 ra1 = *(const float4*)(pA + 64L * lda);
    float4 rb0 = *(const float4*)pB;
    float4 rb1 = *(const float4*)(pB + 64L * ldb);

    As[0][lcol + 0][lrow]      = ra0.x;
    As[0][lcol + 1][lrow]      = ra0.y;
    As[0][lcol + 2][lrow]      = ra0.z;
    As[0][lcol + 3][lrow]      = ra0.w;
    As[0][lcol + 0][lrow + 64] = ra1.x;
    As[0][lcol + 1][lrow + 64] = ra1.y;
    As[0][lcol + 2][lrow + 64] = ra1.z;
    As[0][lcol + 3][lrow + 64] = ra1.w;
    Bs[0][lcol + 0][lrow]      = rb0.x;
    Bs[0][lcol + 1][lrow]      = rb0.y;
    Bs[0][lcol + 2][lrow]      = rb0.z;
    Bs[0][lcol + 3][lrow]      = rb0.w;
    Bs[0][lcol + 0][lrow + 64] = rb1.x;
    Bs[0][lcol + 1][lrow + 64] = rb1.y;
    Bs[0][lcol + 2][lrow + 64] = rb1.z;
    Bs[0][lcol + 3][lrow + 64] = rb1.w;
    __syncthreads();

    int st = 0;
    const int KT = K >> 4;
    for (int kt = 0; kt < KT; kt++) {
        if (kt + 1 < KT) {
            const float* qA = pA + (kt + 1) * BK;
            const float* qB = pB + (kt + 1) * BK;
            ra0 = *(const float4*)qA;
            ra1 = *(const float4*)(qA + 64L * lda);
            rb0 = *(const float4*)qB;
            rb1 = *(const float4*)(qB + 64L * ldb);
        }
#pragma unroll
        for (int k = 0; k < BK; k++) {
            float a[8], b[8];
            *(float4*)(a)     = *(const float4*)&As[st][k][ty * 8];
            *(float4*)(a + 4) = *(const float4*)&As[st][k][ty * 8 + 4];
            *(float4*)(b)     = *(const float4*)&Bs[st][k][tx * 8];
            *(float4*)(b + 4) = *(const float4*)&Bs[st][k][tx * 8 + 4];
#pragma unroll
            for (int i = 0; i < 8; i++)
#pragma unroll
                for (int j = 0; j < 8; j++) acc[i][j] += a[i] * b[j];
        }
        if (kt + 1 < KT) {
            st ^= 1;
            As[st][lcol + 0][lrow]      = ra0.x;
            As[st][lcol + 1][lrow]      = ra0.y;
            As[st][lcol + 2][lrow]      = ra0.z;
            As[st][lcol + 3][lrow]      = ra0.w;
            As[st][lcol + 0][lrow + 64] = ra1.x;
            As[st][lcol + 1][lrow + 64] = ra1.y;
            As[st][lcol + 2][lrow + 64] = ra1.z;
            As[st][lcol + 3][lrow + 64] = ra1.w;
            Bs[st][lcol + 0][lrow]      = rb0.x;
            Bs[st][lcol + 1][lrow]      = rb0.y;
            Bs[st][lcol + 2][lrow]      = rb0.z;
            Bs[st][lcol + 3][lrow]      = rb0.w;
            Bs[st][lcol + 0][lrow + 64] = rb1.x;
            Bs[st][lcol + 1][lrow + 64] = rb1.y;
            Bs[st][lcol + 2][lrow + 64] = rb1.z;
            Bs[st][lcol + 3][lrow + 64] = rb1.w;
            __syncthreads();
        }
    }

    const int crow = m0 + ty * 8;
    const int ccol = n0 + tx * 8;
    float bv[8];
    if (EPI >= 1) {
#pragma unroll
        for (int j = 0; j < 8; j++) bv[j] = bias[ccol + j];
    }
#pragma unroll
    for (int i = 0; i < 8; i++) {
        float o[8];
#pragma unroll
        for (int j = 0; j < 8; j++) {
            float v = acc[i][j];
            if (EPI >= 1) v += bv[j];
            if (EPI == 2) v = gelu_exact(v);
            o[j] = v;
        }
        *(float4*)&C[(long)(crow + i) * ldc + ccol]     = *(float4*)o;
        *(float4*)&C[(long)(crow + i) * ldc + ccol + 4] = *(float4*)(o + 4);
    }
}

// ---------------------------------------------------------------------------
// NN GEMM: C[m][n] = sum_k A[m][k] * B[k][n]   (no bias; used for P @ V)
// ---------------------------------------------------------------------------
__global__ void __launch_bounds__(256, 2)
gemm_nn(const float* __restrict__ A, int lda, long sAb, long sAh,
        const float* __restrict__ B, int ldb, long sBb, long sBh,
        float* __restrict__ C, int ldc, long sCb, long sCh,
        int K)
{
    const int tid = threadIdx.x;
    const int z   = blockIdx.z;
    const int zb  = z >> 3;
    const int zh  = z & 7;
    A += (long)zb * sAb + (long)zh * sAh;
    B += (long)zb * sBb + (long)zh * sBh;
    C += (long)zb * sCb + (long)zh * sCh;

    const int m0 = blockIdx.y * BM;
    const int n0 = blockIdx.x * BN;

    __shared__ float As[2][BK][BM];
    __shared__ float Bs[2][BK][BN];

    const int lrow = tid >> 2;           // A loader: 0..63
    const int lcol = (tid & 3) << 2;
    const float* pA = A + (long)(m0 + lrow) * lda + lcol;

    const int bkrow = tid >> 4;          // B loader: k-row 0..15
    const int bncol = (tid & 15) << 3;   // n col 0..120 (2 float4)
    const float* pB = B + (long)bkrow * ldb + n0 + bncol;

    const int w    = tid >> 5;
    const int lane = tid & 31;
    const int ty   = ((w >> 1) << 2) + (lane >> 3);
    const int tx   = ((w & 1) << 3) + (lane & 7);

    float acc[8][8];
#pragma unroll
    for (int i = 0; i < 8; i++)
#pragma unroll
        for (int j = 0; j < 8; j++) acc[i][j] = 0.0f;

    float4 ra0 = *(const float4*)pA;
    float4 ra1 = *(const float4*)(pA + 64L * lda);
    float4 rb0 = *(const float4*)pB;
    float4 rb1 = *(const float4*)(pB + 4);

    As[0][lcol + 0][lrow]      = ra0.x;
    As[0][lcol + 1][lrow]      = ra0.y;
    As[0][lcol + 2][lrow]      = ra0.z;
    As[0][lcol + 3][lrow]      = ra0.w;
    As[0][lcol + 0][lrow + 64] = ra1.x;
    As[0][lcol + 1][lrow + 64] = ra1.y;
    As[0][lcol + 2][lrow + 64] = ra1.z;
    As[0][lcol + 3][lrow + 64] = ra1.w;
    *(float4*)&Bs[0][bkrow][bncol]     = rb0;
    *(float4*)&Bs[0][bkrow][bncol + 4] = rb1;
    __syncthreads();

    int st = 0;
    const int KT = K >> 4;
    for (int kt = 0; kt < KT; kt++) {
        if (kt + 1 < KT) {
            const float* qA = pA + (kt + 1) * BK;
            const float* qB = pB + (long)(kt + 1) * BK * ldb;
            ra0 = *(const float4*)qA;
            ra1 = *(const float4*)(qA + 64L * lda);
            rb0 = *(const float4*)qB;
            rb1 = *(const float4*)(qB + 4);
        }
#pragma unroll
        for (int k = 0; k < BK; k++) {
            float a[8], b[8];
            *(float4*)(a)     = *(const float4*)&As[st][k][ty * 8];
            *(float4*)(a + 4) = *(const float4*)&As[st][k][ty * 8 + 4];
            *(float4*)(b)     = *(const float4*)&Bs[st][k][tx * 8];
            *(float4*)(b + 4) = *(const float4*)&Bs[st][k][tx * 8 + 4];
#pragma unroll
            for (int i = 0; i < 8; i++)
#pragma unroll
                for (int j = 0; j < 8; j++) acc[i][j] += a[i] * b[j];
        }
        if (kt + 1 < KT) {
            st ^= 1;
            As[st][lcol + 0][lrow]      = ra0.x;
            As[st][lcol + 1][lrow]      = ra0.y;
            As[st][lcol + 2][lrow]      = ra0.z;
            As[st][lcol + 3][lrow]      = ra0.w;
            As[st][lcol + 0][lrow + 64] = ra1.x;
            As[st][lcol + 1][lrow + 64] = ra1.y;
            As[st][lcol + 2][lrow + 64] = ra1.z;
            As[st][lcol + 3][lrow + 64] = ra1.w;
            *(float4*)&Bs[st][bkrow][bncol]     = rb0;
            *(float4*)&Bs[st][bkrow][bncol + 4] = rb1;
            __syncthreads();
        }
    }

    const int crow = m0 + ty * 8;
    const int ccol = n0 + tx * 8;
#pragma unroll
    for (int i = 0; i < 8; i++) {
        *(float4*)&C[(long)(crow + i) * ldc + ccol]     = *(float4*)&acc[i][0];
        *(float4*)&C[(long)(crow + i) * ldc + ccol + 4] = *(float4*)&acc[i][4];
    }
}

// ---------------------------------------------------------------------------
// Fused ALiBi + softmax over rows of S (row = ((b*8+h)*512 + i), width 512).
// val = S * (1/sqrt(128)) - slope_h * |i - j| ; in-place softmax.
// ---------------------------------------------------------------------------
__global__ void __launch_bounds__(256)
softmax_alibi(float* __restrict__ S)
{
    const int r = blockIdx.x;
    const int i = r & 511;
    const int h = (r >> 9) & 7;
    const float slope = exp2f(-(float)(h + 1));
    float* row = S + (long)r * 512;

    const int t = threadIdx.x;
    const float sc = 0.08838834764831845f;   // 1/sqrt(128)

    float2 v = *(float2*)(row + 2 * t);
    const float fi = (float)i;
    const float j0 = (float)(2 * t);
    float v0 = v.x * sc - slope * fabsf(fi - j0);
    float v1 = v.y * sc - slope * fabsf(fi - (j0 + 1.0f));

    __shared__ float sh[8];
    __shared__ float bc;

    // max reduce
    float m = fmaxf(v0, v1);
#pragma unroll
    for (int o = 16; o; o >>= 1) m = fmaxf(m, __shfl_xor_sync(0xffffffffu, m, o));
    if ((t & 31) == 0) sh[t >> 5] = m;
    __syncthreads();
    if (t == 0) {
        float mm = sh[0];
#pragma unroll
        for (int q = 1; q < 8; q++) mm = fmaxf(mm, sh[q]);
        bc = mm;
    }
    __syncthreads();
    m = bc;

    float e0 = expf(v0 - m);
    float e1 = expf(v1 - m);
    float s = e0 + e1;
#pragma unroll
    for (int o = 16; o; o >>= 1) s += __shfl_xor_sync(0xffffffffu, s, o);
    __syncthreads();               // protect sh[] reuse
    if ((t & 31) == 0) sh[t >> 5] = s;
    __syncthreads();
    if (t == 0) {
        float ss = sh[0];
#pragma unroll
        for (int q = 1; q < 8; q++) ss += sh[q];
        bc = 1.0f / ss;
    }
    __syncthreads();
    const float inv = bc;

    float2 o;
    o.x = e0 * inv;
    o.y = e1 * inv;
    *(float2*)(row + 2 * t) = o;
}

// ---------------------------------------------------------------------------
// out = LayerNorm(x + y) * g + b, row width 1024, one block per row.
// ---------------------------------------------------------------------------
__global__ void __launch_bounds__(256)
add_ln(const float* __restrict__ X, const float* __restrict__ Y,
       const float* __restrict__ G, const float* __restrict__ Bt,
       float* __restrict__ O)
{
    const int row = blockIdx.x;
    const long base = (long)row * 1024;
    const int t = threadIdx.x;

    float4 vx = *(const float4*)(X + base + 4 * t);
    float4 vy = *(const float4*)(Y + base + 4 * t);
    float a0 = vx.x + vy.x;
    float a1 = vx.y + vy.y;
    float a2 = vx.z + vy.z;
    float a3 = vx.w + vy.w;

    float s = a0 + a1 + a2 + a3;
    float q = a0 * a0 + a1 * a1 + a2 * a2 + a3 * a3;

    __shared__ float2 sh[8];
    __shared__ float2 res;
#pragma unroll
    for (int o = 16; o; o >>= 1) {
        s += __shfl_xor_sync(0xffffffffu, s, o);
        q += __shfl_xor_sync(0xffffffffu, q, o);
    }
    if ((t & 31) == 0) sh[t >> 5] = make_float2(s, q);
    __syncthreads();
    if (t == 0) {
        float ss = 0.0f, qq = 0.0f;
#pragma unroll
        for (int k = 0; k < 8; k++) { ss += sh[k].x; qq += sh[k].y; }
        res = make_float2(ss, qq);
    }
    __syncthreads();

    const float mean = res.x * (1.0f / 1024.0f);
    const float var  = res.y * (1.0f / 1024.0f) - mean * mean;
    const float inv  = rsqrtf(var + 1e-5f);

    float4 g4 = *(const float4*)(G + 4 * t);
    float4 b4 = *(const float4*)(Bt + 4 * t);
    float4 o;
    o.x = (a0 - mean) * inv * g4.x + b4.x;
    o.y = (a1 - mean) * inv * g4.y + b4.y;
    o.z = (a2 - mean) * inv * g4.z + b4.z;
    o.w = (a3 - mean) * inv * g4.w + b4.w;
    *(float4*)(O + base + 4 * t) = o;
}

// ---------------------------------------------------------------------------
// Host orchestration
// ---------------------------------------------------------------------------
extern "C" void kernel_launch(void* const* d_in, const int* in_sizes, int n_in,
                              void* d_out, int out_size)
{
    (void)in_sizes; (void)n_in; (void)out_size;

    const float* x      = (const float*)d_in[0];   // (8,2048,128) == (4096,512)
    const float* pre_w  = (const float*)d_in[1];   // (1024,512)
    const float* pre_b  = (const float*)d_in[2];   // (1024)
    const float* in_w   = (const float*)d_in[3];   // (6,3072,1024)
    const float* in_b   = (const float*)d_in[4];   // (6,3072)
    const float* out_w  = (const float*)d_in[5];   // (6,1024,1024)
    const float* out_b  = (const float*)d_in[6];   // (6,1024)
    const float* ln1_g  = (const float*)d_in[7];
    const float* ln1_b  = (const float*)d_in[8];
    const float* ff1_w  = (const float*)d_in[9];   // (6,1024,1024)
    const float* ff1_b  = (const float*)d_in[10];
    const float* ff2_w  = (const float*)d_in[11];  // (6,1024,1024)
    const float* ff2_b  = (const float*)d_in[12];
    const float* ln2_g  = (const float*)d_in[13];
    const float* ln2_b  = (const float*)d_in[14];
    const float* post_w = (const float*)d_in[15];  // (1024,1024)
    const float* post_b = (const float*)d_in[16];

    float *X, *QKV, *S, *O, *T1, *T2;
    cudaGetSymbolAddress((void**)&X,   g_X);
    cudaGetSymbolAddress((void**)&QKV, g_QKV);
    cudaGetSymbolAddress((void**)&S,   g_S);
    cudaGetSymbolAddress((void**)&O,   g_O);
    cudaGetSymbolAddress((void**)&T1,  g_T1);
    cudaGetSymbolAddress((void**)&T2,  g_T2);

    const dim3 blk(256);

    // pre-projection: (4096,512) @ (1024,512)^T -> X (4096,1024)
    gemm_tn<1><<<dim3(8, 32, 1), blk>>>(
        x, 512, 0, 0,  pre_w, 512, 0, 0,  pre_b,
        X, 1024, 0, 0,  512);

    const long sQKVb = 512L * 3072;     // per-batch stride inside QKV
    const long sSb   = 8L * 512 * 512;  // per-batch stride inside S
    const long sSh   = 512L * 512;      // per-head stride inside S
    const long sXb   = 512L * 1024;     // per-batch stride inside X/O

    for (int l = 0; l < 6; l++) {
        const float* iw  = in_w  + (long)l * 3072 * 1024;
        const float* ib  = in_b  + (long)l * 3072;
        const float* ow  = out_w + (long)l * 1024 * 1024;
        const float* ob  = out_b + (long)l * 1024;
        const float* f1w = ff1_w + (long)l * 1024 * 1024;
        const float* f1b = ff1_b + (long)l * 1024;
        const float* f2w = ff2_w + (long)l * 1024 * 1024;
        const float* f2b = ff2_b + (long)l * 1024;
        const float* g1  = ln1_g + (long)l * 1024;
        const float* b1  = ln1_b + (long)l * 1024;
        const float* g2  = ln2_g + (long)l * 1024;
        const float* b2  = ln2_b + (long)l * 1024;

        // QKV = X @ in_w^T + in_b : (4096,1024) x (3072,1024)^T
        gemm_tn<1><<<dim3(24, 32, 1), blk>>>(
            X, 1024, 0, 0,  iw, 1024, 0, 0,  ib,
            QKV, 3072, 0, 0,  1024);

        // scores S[b,h] = Q[b,h] @ K[b,h]^T  (512x512, K=128), z = b*8+h
        gemm_tn<0><<<dim3(4, 4, 64), blk>>>(
            QKV,        3072, sQKVb, 128,
            QKV + 1024, 3072, sQKVb, 128,
            nullptr,
            S, 512, sSb, sSh,  128);

        // softmax with ALiBi + 1/sqrt(Dh) scale (in place)
        softmax_alibi<<<32768, blk>>>(S);

        // O[b,h] = P[b,h] @ V[b,h]  (512x128, K=512)
        gemm_nn<<<dim3(1, 4, 64), blk>>>(
            S,          512,  sSb,   sSh,
            QKV + 2048, 3072, sQKVb, 128,
            O, 1024, sXb, 128,  512);

        // attention output projection
        gemm_tn<1><<<dim3(8, 32, 1), blk>>>(
            O, 1024, 0, 0,  ow, 1024, 0, 0,  ob,
            T1, 1024, 0, 0,  1024);

        // X = LN(X + T1)
        add_ln<<<4096, blk>>>(X, T1, g1, b1, X);

        // FF1 (+ exact GELU)
        gemm_tn<2><<<dim3(8, 32, 1), blk>>>(
            X, 1024, 0, 0,  f1w, 1024, 0, 0,  f1b,
            T1, 1024, 0, 0,  1024);

        // FF2
        gemm_tn<1><<<dim3(8, 32, 1), blk>>>(
            T1, 1024, 0, 0,  f2w, 1024, 0, 0,  f2b,
            T2, 1024, 0, 0,  1024);

        // X = LN(X + T2)
        add_ln<<<4096, blk>>>(X, T2, g2, b2, X);
    }

    // post projection -> d_out (4096,1024)
    gemm_tn<1><<<dim3(8, 32, 1), blk>>>(
        X, 1024, 0, 0,  post_w, 1024, 0, 0,  post_b,
        (float*)d_out, 1024, 0, 0,  1024);
}